// round 4
// baseline (speedup 1.0000x reference)
#include <cuda_runtime.h>
#include <cstdint>

// ============================================================================
// Problem constants
// ============================================================================
#define DIMV     1024
#define BATCH    32
#define SEQ      2048
#define M_TOTAL  (BATCH * SEQ)        // 65536
#define M_TILE   128
#define N_TILE   256
#define K_TILE   32
#define K_TILES  (DIMV / K_TILE)      // 32
#define M_TILES  (M_TOTAL / M_TILE)   // 512
#define N_TILES  (DIMV / N_TILE)      // 4
#define SSPLIT   8                    // context kernel s-split

// Scratch (static device globals — no allocation)
__device__ float g_W1t[DIMV * DIMV];          // W1_enc transposed [n][k], tf32-rounded
__device__ float g_hb[BATCH * DIMV];          // hid_proj + b1
__device__ float g_ep[N_TILES * M_TOTAL];     // partial e per n-tile
__device__ float g_alpha[BATCH * SEQ];        // softmax weights
__device__ float g_cpart[SSPLIT * BATCH * DIMV];  // context partials

// ============================================================================
// Inline PTX helpers (base-arch only: no tcgen05 / no TMA)
// ============================================================================
__device__ __forceinline__ uint32_t smem_to_u32(const void* p) {
    uint32_t a;
    asm("{ .reg .u64 t; cvta.to.shared.u64 t, %1; cvt.u32.u64 %0, t; }"
        : "=r"(a) : "l"(p));
    return a;
}

__device__ __forceinline__ void cp_async16(uint32_t smem_dst, const void* gsrc) {
    asm volatile("cp.async.cg.shared.global [%0], [%1], 16;"
                 :: "r"(smem_dst), "l"(gsrc) : "memory");
}
#define CP_ASYNC_COMMIT() asm volatile("cp.async.commit_group;" ::: "memory")
#define CP_ASYNC_WAIT0()  asm volatile("cp.async.wait_group 0;" ::: "memory")

__device__ __forceinline__ void ldsm_x4(uint32_t& d0, uint32_t& d1,
                                        uint32_t& d2, uint32_t& d3, uint32_t addr) {
    asm volatile("ldmatrix.sync.aligned.m8n8.x4.shared.b16 {%0,%1,%2,%3}, [%4];"
                 : "=r"(d0), "=r"(d1), "=r"(d2), "=r"(d3) : "r"(addr));
}

__device__ __forceinline__ void mma_tf32(float* c, uint32_t a0, uint32_t a1,
                                         uint32_t a2, uint32_t a3,
                                         uint32_t b0, uint32_t b1) {
    asm volatile(
        "mma.sync.aligned.m16n8k8.row.col.f32.tf32.tf32.f32 "
        "{%0,%1,%2,%3}, {%4,%5,%6,%7}, {%8,%9}, {%0,%1,%2,%3};"
        : "+f"(c[0]), "+f"(c[1]), "+f"(c[2]), "+f"(c[3])
        : "r"(a0), "r"(a1), "r"(a2), "r"(a3), "r"(b0), "r"(b1));
}

__device__ __forceinline__ uint32_t cvt_tf32(uint32_t x) {
    uint32_t y;
    asm("cvt.rna.tf32.f32 %0, %1;" : "=r"(y) : "r"(x));
    return y;
}

__device__ __forceinline__ float tanh_approx(float x) {
    float y;
    asm("tanh.approx.f32 %0, %1;" : "=f"(y) : "f"(x));
    return y;
}

// ============================================================================
// Kernel 0: transpose + tf32-round W1_enc:  g_W1t[n][k] = rna_tf32(W1[k][n])
// grid (32, 32), threads (32, 8)
// ============================================================================
__global__ void __launch_bounds__(256) transpose_kernel(const float* __restrict__ W1)
{
    __shared__ float t[32][33];
    int bx = blockIdx.x, by = blockIdx.y;
    int tx = threadIdx.x, ty = threadIdx.y;
#pragma unroll
    for (int j = 0; j < 32; j += 8)
        t[ty + j][tx] = W1[(size_t)(by * 32 + ty + j) * DIMV + bx * 32 + tx];
    __syncthreads();
#pragma unroll
    for (int j = 0; j < 32; j += 8) {
        uint32_t v = __float_as_uint(t[tx][ty + j]);
        g_W1t[(size_t)(bx * 32 + ty + j) * DIMV + by * 32 + tx] =
            __uint_as_float(cvt_tf32(v));
    }
}

// ============================================================================
// Kernel 1: hb[b,e] = b1[e] + sum_d hidden[b,d] * W1[DIMV + d, e]   (fp32 exact)
// grid (32, 8), 128 threads
// ============================================================================
__global__ void __launch_bounds__(128) hidproj_kernel(
    const float* __restrict__ hidden, const float* __restrict__ W1,
    const float* __restrict__ b1)
{
    __shared__ float sh[DIMV];
    int b = blockIdx.x;
    int e = blockIdx.y * 128 + threadIdx.x;
    for (int i = threadIdx.x; i < DIMV; i += 128)
        sh[i] = hidden[b * DIMV + i];
    __syncthreads();

    float acc = b1[e];
    const float* wp = W1 + (size_t)DIMV * DIMV + e;
#pragma unroll 8
    for (int d = 0; d < DIMV; d++)
        acc += sh[d] * wp[(size_t)d * DIMV];
    g_hb[b * DIMV + e] = acc;
}

// ============================================================================
// Kernel 2: fused tf32 mma.sync GEMM + tanh + dot(w2) epilogue
// CTA tile 128(m) x 256(n), K streamed in 32-chunks, double-buffered cp.async.
// 512 threads = 16 warps, warp grid 2(m) x 8(n), warp tile 64x32.
// grid (4 n-tiles, 512 m-tiles)
// ============================================================================
#define STAGE_A_BYTES  (M_TILE * 128)              // 16384
#define STAGE_B_BYTES  (N_TILE * 128)              // 32768
#define STAGE_BYTES    (STAGE_A_BYTES + STAGE_B_BYTES)  // 49152
#define OFF_EPBUF      (2 * STAGE_BYTES)           // 98304
#define OFF_HBS        (OFF_EPBUF + 8 * 128 * 4)   // 102400
#define OFF_W2S        (OFF_HBS + 256 * 4)         // 103424
#define SMEM_GEMM      (OFF_W2S + 256 * 4)         // 104448

// swizzle: 16B chunk q within a 128B row of index `row` -> q ^ (row & 7)
__global__ void __launch_bounds__(512, 1) gemm_tanh_kernel(
    const float* __restrict__ enc, const float* __restrict__ w2)
{
    extern __shared__ char smem[];
    uint32_t smem_u32 = smem_to_u32(smem);

    int tid    = threadIdx.x;
    int lane   = tid & 31;
    int wid    = tid >> 5;
    int warp_m = wid >> 3;          // 0..1
    int warp_n = wid & 7;           // 0..7
    int m0     = blockIdx.y * M_TILE;
    int n0     = blockIdx.x * N_TILE;
    int b      = blockIdx.y >> 4;   // m0 / SEQ

    float* epbuf = (float*)(smem + OFF_EPBUF);   // [8][128]
    float* hbs   = (float*)(smem + OFF_HBS);     // [256]
    float* w2s   = (float*)(smem + OFF_W2S);     // [256]
    if (tid < 256) {
        hbs[tid] = g_hb[b * DIMV + n0 + tid];
        w2s[tid] = w2[n0 + tid];
    }

    // ---- per-thread ldmatrix lane decomposition ----
    int r    = lane & 7;    // row within 8-row submatrix
    int i4   = lane >> 3;   // which of the 4 submatrices this lane addresses
    int hi8  = (i4 & 1) * 8;   // A: submatrix 1,3 are rows +8
    int acb  = i4 >> 1;        // A: submatrix 2,3 are k-chunk +1
    int bnt  = i4 >> 1;        // B: submatrix 2,3 are next n-tile
    int bcb  = i4 & 1;         // B: submatrix 1,3 are k-chunk +1

    int aoff[4];
#pragma unroll
    for (int mt = 0; mt < 4; mt++)
        aoff[mt] = (warp_m * 64 + mt * 16 + hi8 + r) * 128;
    int boff[2];
#pragma unroll
    for (int p = 0; p < 2; p++)
        boff[p] = STAGE_A_BYTES + (warp_n * 32 + (2 * p + bnt) * 8 + r) * 128;

    float acc[4][4][4];
#pragma unroll
    for (int mt = 0; mt < 4; mt++)
#pragma unroll
        for (int nt = 0; nt < 4; nt++)
#pragma unroll
            for (int f = 0; f < 4; f++) acc[mt][nt][f] = 0.0f;

    const float* Abase = enc + (size_t)m0 * DIMV;
    const float* Bbase = g_W1t + (size_t)n0 * DIMV;

    // per-thread load assignments: A 2 chunks, B 4 chunks (16B each)
    int a_row0 = tid >> 3,           a_q0 = tid & 7;
    int a_row1 = (tid + 512) >> 3,   a_q1 = tid & 7;

    // prologue: stage 0, kc 0
    {
        uint32_t As = smem_u32, Bs = smem_u32 + STAGE_A_BYTES;
        cp_async16(As + a_row0 * 128 + ((a_q0 ^ (a_row0 & 7)) << 4),
                   Abase + (size_t)a_row0 * DIMV + a_q0 * 4);
        cp_async16(As + a_row1 * 128 + ((a_q1 ^ (a_row1 & 7)) << 4),
                   Abase + (size_t)a_row1 * DIMV + a_q1 * 4);
#pragma unroll
        for (int j = 0; j < 4; j++) {
            int c = tid + j * 512, row = c >> 3, q = c & 7;
            cp_async16(Bs + row * 128 + ((q ^ (row & 7)) << 4),
                       Bbase + (size_t)row * DIMV + q * 4);
        }
        CP_ASYNC_COMMIT();
    }

    for (int kc = 0; kc < K_TILES; kc++) {
        int cur = kc & 1;
        CP_ASYNC_WAIT0();
        __syncthreads();

        if (kc < K_TILES - 1) {
            uint32_t As = smem_u32 + (cur ^ 1) * STAGE_BYTES;
            uint32_t Bs = As + STAGE_A_BYTES;
            const float* Ag = Abase + (kc + 1) * K_TILE;
            const float* Bg = Bbase + (kc + 1) * K_TILE;
            cp_async16(As + a_row0 * 128 + ((a_q0 ^ (a_row0 & 7)) << 4),
                       Ag + (size_t)a_row0 * DIMV + a_q0 * 4);
            cp_async16(As + a_row1 * 128 + ((a_q1 ^ (a_row1 & 7)) << 4),
                       Ag + (size_t)a_row1 * DIMV + a_q1 * 4);
#pragma unroll
            for (int j = 0; j < 4; j++) {
                int c = tid + j * 512, row = c >> 3, q = c & 7;
                cp_async16(Bs + row * 128 + ((q ^ (row & 7)) << 4),
                           Bg + (size_t)row * DIMV + q * 4);
            }
            CP_ASYNC_COMMIT();
        }

        uint32_t Ssm = smem_u32 + cur * STAGE_BYTES;
#pragma unroll
        for (int ks = 0; ks < 4; ks++) {
            uint32_t a[4][4];
#pragma unroll
            for (int mt = 0; mt < 4; mt++) {
                uint32_t addr = Ssm + aoff[mt] + ((((ks * 2) | acb) ^ r) << 4);
                ldsm_x4(a[mt][0], a[mt][1], a[mt][2], a[mt][3], addr);
                a[mt][0] = cvt_tf32(a[mt][0]);
                a[mt][1] = cvt_tf32(a[mt][1]);
                a[mt][2] = cvt_tf32(a[mt][2]);
                a[mt][3] = cvt_tf32(a[mt][3]);
            }
#pragma unroll
            for (int p = 0; p < 2; p++) {
                uint32_t b0, b1, b2, b3;   // b0,b1 -> nt=2p ; b2,b3 -> nt=2p+1
                uint32_t addr = Ssm + boff[p] + ((((ks * 2) | bcb) ^ r) << 4);
                ldsm_x4(b0, b1, b2, b3, addr);
#pragma unroll
                for (int mt = 0; mt < 4; mt++) {
                    mma_tf32(acc[mt][2 * p],     a[mt][0], a[mt][1], a[mt][2], a[mt][3], b0, b1);
                    mma_tf32(acc[mt][2 * p + 1], a[mt][0], a[mt][1], a[mt][2], a[mt][3], b2, b3);
                }
            }
        }
    }

    // ---- fused epilogue: e_partial[row] = sum_n tanh(acc + hb[n]) * w2[n] ----
    int g  = lane >> 2;
    int t4 = lane & 3;
#pragma unroll
    for (int mt = 0; mt < 4; mt++) {
        float e0 = 0.0f, e1 = 0.0f;
#pragma unroll
        for (int nt = 0; nt < 4; nt++) {
            int n = warp_n * 32 + nt * 8 + 2 * t4;
            float h0 = hbs[n], h1 = hbs[n + 1];
            float v0 = w2s[n], v1 = w2s[n + 1];
            e0 += tanh_approx(acc[mt][nt][0] + h0) * v0
                + tanh_approx(acc[mt][nt][1] + h1) * v1;
            e1 += tanh_approx(acc[mt][nt][2] + h0) * v0
                + tanh_approx(acc[mt][nt][3] + h1) * v1;
        }
        e0 += __shfl_xor_sync(0xFFFFFFFF, e0, 1);
        e0 += __shfl_xor_sync(0xFFFFFFFF, e0, 2);
        e1 += __shfl_xor_sync(0xFFFFFFFF, e1, 1);
        e1 += __shfl_xor_sync(0xFFFFFFFF, e1, 2);
        if (t4 == 0) {
            int rl = warp_m * 64 + mt * 16 + g;
            epbuf[warp_n * 128 + rl]     = e0;
            epbuf[warp_n * 128 + rl + 8] = e1;
        }
    }
    __syncthreads();
    if (tid < 128) {
        float s = 0.0f;
#pragma unroll
        for (int w = 0; w < 8; w++) s += epbuf[w * 128 + tid];
        g_ep[(size_t)blockIdx.x * M_TOTAL + m0 + tid] = s;
    }
}

// ============================================================================
// Kernel 3: softmax over S -> alpha. grid 32, 256 threads
// ============================================================================
__global__ void __launch_bounds__(256) softmax_kernel()
{
    __shared__ float se[SEQ];
    __shared__ float red[256];
    int b = blockIdx.x;
    int tid = threadIdx.x;

    float mx = -1e30f;
    for (int s = tid; s < SEQ; s += 256) {
        int row = b * SEQ + s;
        float v = g_ep[row] + g_ep[M_TOTAL + row]
                + g_ep[2 * M_TOTAL + row] + g_ep[3 * M_TOTAL + row];
        se[s] = v;
        mx = fmaxf(mx, v);
    }
    red[tid] = mx;
    __syncthreads();
    for (int s = 128; s > 0; s >>= 1) {
        if (tid < s) red[tid] = fmaxf(red[tid], red[tid + s]);
        __syncthreads();
    }
    mx = red[0];
    __syncthreads();

    float sum = 0.0f;
    for (int s = tid; s < SEQ; s += 256) {
        float ex = __expf(se[s] - mx);
        se[s] = ex;
        sum += ex;
    }
    red[tid] = sum;
    __syncthreads();
    for (int s = 128; s > 0; s >>= 1) {
        if (tid < s) red[tid] += red[tid + s];
        __syncthreads();
    }
    float inv = 1.0f / red[0];
    for (int s = tid; s < SEQ; s += 256)
        g_alpha[b * SEQ + s] = se[s] * inv;
}

// ============================================================================
// Kernel 4: context partials — split S 8 ways for memory-level parallelism
// grid (8 d-blocks, 32 batch, 8 s-chunks), 128 threads
// ============================================================================
__global__ void __launch_bounds__(128) ctx_partial_kernel(const float* __restrict__ enc)
{
    __shared__ float sa[SEQ / SSPLIT];   // 256
    int b  = blockIdx.y;
    int d  = blockIdx.x * 128 + threadIdx.x;
    int s0 = blockIdx.z * (SEQ / SSPLIT);

    for (int i = threadIdx.x; i < SEQ / SSPLIT; i += 128)
        sa[i] = g_alpha[b * SEQ + s0 + i];
    __syncthreads();

    const float* ep = enc + ((size_t)b * SEQ + s0) * DIMV + d;
    float a0 = 0.f, a1 = 0.f, a2 = 0.f, a3 = 0.f;
#pragma unroll 2
    for (int s = 0; s < SEQ / SSPLIT; s += 8) {
        a0 += sa[s + 0] * ep[(size_t)(s + 0) * DIMV];
        a1 += sa[s + 1] * ep[(size_t)(s + 1) * DIMV];
        a2 += sa[s + 2] * ep[(size_t)(s + 2) * DIMV];
        a3 += sa[s + 3] * ep[(size_t)(s + 3) * DIMV];
        a0 += sa[s + 4] * ep[(size_t)(s + 4) * DIMV];
        a1 += sa[s + 5] * ep[(size_t)(s + 5) * DIMV];
        a2 += sa[s + 6] * ep[(size_t)(s + 6) * DIMV];
        a3 += sa[s + 7] * ep[(size_t)(s + 7) * DIMV];
    }
    g_cpart[((size_t)blockIdx.z * BATCH + b) * DIMV + d] = (a0 + a1) + (a2 + a3);
}

// Kernel 5: combine partials -> out. grid 32 x 1024 threads
__global__ void __launch_bounds__(1024) ctx_combine_kernel(float* __restrict__ out)
{
    int i = blockIdx.x * 1024 + threadIdx.x;   // b*DIMV + d
    float s = 0.0f;
#pragma unroll
    for (int z = 0; z < SSPLIT; z++)
        s += g_cpart[(size_t)z * BATCH * DIMV + i];
    out[i] = s;
}

// ============================================================================
// Launch
// ============================================================================
extern "C" void kernel_launch(void* const* d_in, const int* in_sizes, int n_in,
                              void* d_out, int out_size)
{
    (void)in_sizes; (void)n_in; (void)out_size;
    const float* hidden = (const float*)d_in[0];   // [32, 1024]
    const float* enc    = (const float*)d_in[1];   // [32, 2048, 1024]
    const float* W1     = (const float*)d_in[2];   // [2048, 1024]
    const float* b1     = (const float*)d_in[3];   // [1024]
    const float* w2     = (const float*)d_in[4];   // [1024]
    float* out          = (float*)d_out;           // [32, 1024]

    cudaFuncSetAttribute(gemm_tanh_kernel,
                         cudaFuncAttributeMaxDynamicSharedMemorySize, SMEM_GEMM);

    transpose_kernel<<<dim3(32, 32), dim3(32, 8)>>>(W1);
    hidproj_kernel<<<dim3(32, 8), 128>>>(hidden, W1, b1);
    gemm_tanh_kernel<<<dim3(N_TILES, M_TILES), 512, SMEM_GEMM>>>(enc, w2);
    softmax_kernel<<<32, 256>>>();
    ctx_partial_kernel<<<dim3(8, 32, 8), 128>>>(enc);
    ctx_combine_kernel<<<32, 1024>>>(out);
}

// round 5
// speedup vs baseline: 1.6375x; 1.6375x over previous
#include <cuda_runtime.h>
#include <cuda_fp16.h>
#include <cstdint>

// ============================================================================
// Problem constants
// ============================================================================
#define DIMV     1024
#define BATCH    32
#define SEQ      2048
#define M_TOTAL  (BATCH * SEQ)        // 65536
#define M_TILE   128
#define N_TILE   256
#define K_TILE   64                   // 64 fp16 = 128 bytes per SMEM row
#define K_TILES  (DIMV / K_TILE)      // 16
#define M_TILES  (M_TOTAL / M_TILE)   // 512
#define N_TILES  (DIMV / N_TILE)      // 4
#define SSPLIT   8                    // context kernel s-split

// Scratch (static device globals — no allocation)
__device__ __half g_enc16[(size_t)M_TOTAL * DIMV];   // enc in fp16 (128 MB)
__device__ __half g_W1t16[DIMV * DIMV];              // W1_enc transposed [n][k], fp16
__device__ float  g_hb[BATCH * DIMV];                // hid_proj + b1
__device__ float  g_ep[N_TILES * M_TOTAL];           // partial e per n-tile
__device__ float  g_alpha[BATCH * SEQ];              // softmax weights
__device__ float  g_cpart[SSPLIT * BATCH * DIMV];    // context partials

// ============================================================================
// Inline PTX helpers (base-arch only: no tcgen05 / no TMA)
// ============================================================================
__device__ __forceinline__ uint32_t smem_to_u32(const void* p) {
    uint32_t a;
    asm("{ .reg .u64 t; cvta.to.shared.u64 t, %1; cvt.u32.u64 %0, t; }"
        : "=r"(a) : "l"(p));
    return a;
}

__device__ __forceinline__ void cp_async16(uint32_t smem_dst, const void* gsrc) {
    asm volatile("cp.async.cg.shared.global [%0], [%1], 16;"
                 :: "r"(smem_dst), "l"(gsrc) : "memory");
}
#define CP_ASYNC_COMMIT() asm volatile("cp.async.commit_group;" ::: "memory")
#define CP_ASYNC_WAIT0()  asm volatile("cp.async.wait_group 0;" ::: "memory")

__device__ __forceinline__ void ldsm_x4(uint32_t& d0, uint32_t& d1,
                                        uint32_t& d2, uint32_t& d3, uint32_t addr) {
    asm volatile("ldmatrix.sync.aligned.m8n8.x4.shared.b16 {%0,%1,%2,%3}, [%4];"
                 : "=r"(d0), "=r"(d1), "=r"(d2), "=r"(d3) : "r"(addr));
}

// f16 MMA: D(16x8,f32) += A(16x16,f16) * B(16x8,f16)
__device__ __forceinline__ void mma_f16(float* c, uint32_t a0, uint32_t a1,
                                        uint32_t a2, uint32_t a3,
                                        uint32_t b0, uint32_t b1) {
    asm volatile(
        "mma.sync.aligned.m16n8k16.row.col.f32.f16.f16.f32 "
        "{%0,%1,%2,%3}, {%4,%5,%6,%7}, {%8,%9}, {%0,%1,%2,%3};"
        : "+f"(c[0]), "+f"(c[1]), "+f"(c[2]), "+f"(c[3])
        : "r"(a0), "r"(a1), "r"(a2), "r"(a3), "r"(b0), "r"(b1));
}

__device__ __forceinline__ float tanh_approx(float x) {
    float y;
    asm("tanh.approx.f32 %0, %1;" : "=f"(y) : "f"(x));
    return y;
}

// ============================================================================
// Kernel A: convert enc (fp32) -> g_enc16 (fp16). 8 elems/thread.
// grid 8192 x 1024
// ============================================================================
__global__ void __launch_bounds__(1024) enc16_kernel(const float* __restrict__ enc)
{
    size_t i = ((size_t)blockIdx.x * 1024 + threadIdx.x) * 8;
    float4 v0 = *(const float4*)(enc + i);
    float4 v1 = *(const float4*)(enc + i + 4);
    __half2 h0 = __floats2half2_rn(v0.x, v0.y);
    __half2 h1 = __floats2half2_rn(v0.z, v0.w);
    __half2 h2 = __floats2half2_rn(v1.x, v1.y);
    __half2 h3 = __floats2half2_rn(v1.z, v1.w);
    uint4 o;
    o.x = *(uint32_t*)&h0; o.y = *(uint32_t*)&h1;
    o.z = *(uint32_t*)&h2; o.w = *(uint32_t*)&h3;
    *(uint4*)(g_enc16 + i) = o;
}

// ============================================================================
// Kernel 0: transpose W1_enc -> fp16:  g_W1t16[n][k] = half(W1[k][n])
// grid (32, 32), threads (32, 8)
// ============================================================================
__global__ void __launch_bounds__(256) transpose_kernel(const float* __restrict__ W1)
{
    __shared__ float t[32][33];
    int bx = blockIdx.x, by = blockIdx.y;
    int tx = threadIdx.x, ty = threadIdx.y;
#pragma unroll
    for (int j = 0; j < 32; j += 8)
        t[ty + j][tx] = W1[(size_t)(by * 32 + ty + j) * DIMV + bx * 32 + tx];
    __syncthreads();
#pragma unroll
    for (int j = 0; j < 32; j += 8)
        g_W1t16[(size_t)(bx * 32 + ty + j) * DIMV + by * 32 + tx] =
            __float2half_rn(t[tx][ty + j]);
}

// ============================================================================
// Kernel 1: hb[b,e] = b1[e] + sum_d hidden[b,d] * W1[DIMV + d, e]   (fp32 exact)
// grid (32, 8), 128 threads
// ============================================================================
__global__ void __launch_bounds__(128) hidproj_kernel(
    const float* __restrict__ hidden, const float* __restrict__ W1,
    const float* __restrict__ b1)
{
    __shared__ float sh[DIMV];
    int b = blockIdx.x;
    int e = blockIdx.y * 128 + threadIdx.x;
    for (int i = threadIdx.x; i < DIMV; i += 128)
        sh[i] = hidden[b * DIMV + i];
    __syncthreads();

    float acc = b1[e];
    const float* wp = W1 + (size_t)DIMV * DIMV + e;
#pragma unroll 8
    for (int d = 0; d < DIMV; d++)
        acc += sh[d] * wp[(size_t)d * DIMV];
    g_hb[b * DIMV + e] = acc;
}

// ============================================================================
// Kernel 2: fused fp16 mma.sync GEMM + tanh + dot(w2) epilogue
// CTA tile 128(m) x 256(n), K streamed in 64-chunks, double-buffered cp.async.
// 512 threads = 16 warps, warp grid 2(m) x 8(n), warp tile 64x32.
// grid (4 n-tiles, 512 m-tiles)
// ============================================================================
#define STAGE_A_BYTES  (M_TILE * 128)              // 16384 (128 rows x 64 fp16)
#define STAGE_B_BYTES  (N_TILE * 128)              // 32768 (256 rows x 64 fp16)
#define STAGE_BYTES    (STAGE_A_BYTES + STAGE_B_BYTES)  // 49152
#define OFF_EPBUF      (2 * STAGE_BYTES)           // 98304
#define OFF_HBS        (OFF_EPBUF + 8 * 128 * 4)   // 102400
#define OFF_W2S        (OFF_HBS + 256 * 4)         // 103424
#define SMEM_GEMM      (OFF_W2S + 256 * 4)         // 104448

// swizzle: 16B chunk q within a 128B row of index `row` -> q ^ (row & 7)
__global__ void __launch_bounds__(512, 1) gemm_tanh_kernel(const float* __restrict__ w2)
{
    extern __shared__ char smem[];
    uint32_t smem_u32 = smem_to_u32(smem);

    int tid    = threadIdx.x;
    int lane   = tid & 31;
    int wid    = tid >> 5;
    int warp_m = wid >> 3;          // 0..1
    int warp_n = wid & 7;           // 0..7
    int m0     = blockIdx.y * M_TILE;
    int n0     = blockIdx.x * N_TILE;
    int b      = blockIdx.y >> 4;   // m0 / SEQ

    float* epbuf = (float*)(smem + OFF_EPBUF);   // [8][128]
    float* hbs   = (float*)(smem + OFF_HBS);     // [256]
    float* w2s   = (float*)(smem + OFF_W2S);     // [256]
    if (tid < 256) {
        hbs[tid] = g_hb[b * DIMV + n0 + tid];
        w2s[tid] = w2[n0 + tid];
    }

    // ---- per-thread ldmatrix lane decomposition ----
    int r    = lane & 7;    // row within 8-row submatrix
    int i4   = lane >> 3;   // which of the 4 submatrices this lane addresses
    int hi8  = (i4 & 1) * 8;   // A: submatrix 1,3 are rows +8
    int acb  = i4 >> 1;        // A: submatrix 2,3 are k-chunk +1
    int bnt  = i4 >> 1;        // B: submatrix 2,3 are n +8
    int bcb  = i4 & 1;         // B: submatrix 1,3 are k-chunk +1

    int aoff[4];
#pragma unroll
    for (int mt = 0; mt < 4; mt++)
        aoff[mt] = (warp_m * 64 + mt * 16 + hi8 + r) * 128;
    int boff[2];
#pragma unroll
    for (int p = 0; p < 2; p++)
        boff[p] = STAGE_A_BYTES + (warp_n * 32 + (2 * p + bnt) * 8 + r) * 128;

    float acc[4][4][4];
#pragma unroll
    for (int mt = 0; mt < 4; mt++)
#pragma unroll
        for (int nt = 0; nt < 4; nt++)
#pragma unroll
            for (int f = 0; f < 4; f++) acc[mt][nt][f] = 0.0f;

    const __half* Abase = g_enc16 + (size_t)m0 * DIMV;
    const __half* Bbase = g_W1t16 + (size_t)n0 * DIMV;

    // per-thread load assignments (16B chunks = 8 fp16): A 2, B 4
    int a_row0 = tid >> 3,           a_q0 = tid & 7;
    int a_row1 = (tid + 512) >> 3,   a_q1 = tid & 7;

    // prologue: stage 0, kc 0
    {
        uint32_t As = smem_u32, Bs = smem_u32 + STAGE_A_BYTES;
        cp_async16(As + a_row0 * 128 + ((a_q0 ^ (a_row0 & 7)) << 4),
                   Abase + (size_t)a_row0 * DIMV + a_q0 * 8);
        cp_async16(As + a_row1 * 128 + ((a_q1 ^ (a_row1 & 7)) << 4),
                   Abase + (size_t)a_row1 * DIMV + a_q1 * 8);
#pragma unroll
        for (int j = 0; j < 4; j++) {
            int c = tid + j * 512, row = c >> 3, q = c & 7;
            cp_async16(Bs + row * 128 + ((q ^ (row & 7)) << 4),
                       Bbase + (size_t)row * DIMV + q * 8);
        }
        CP_ASYNC_COMMIT();
    }

    for (int kc = 0; kc < K_TILES; kc++) {
        int cur = kc & 1;
        CP_ASYNC_WAIT0();
        __syncthreads();

        if (kc < K_TILES - 1) {
            uint32_t As = smem_u32 + (cur ^ 1) * STAGE_BYTES;
            uint32_t Bs = As + STAGE_A_BYTES;
            const __half* Ag = Abase + (kc + 1) * K_TILE;
            const __half* Bg = Bbase + (kc + 1) * K_TILE;
            cp_async16(As + a_row0 * 128 + ((a_q0 ^ (a_row0 & 7)) << 4),
                       Ag + (size_t)a_row0 * DIMV + a_q0 * 8);
            cp_async16(As + a_row1 * 128 + ((a_q1 ^ (a_row1 & 7)) << 4),
                       Ag + (size_t)a_row1 * DIMV + a_q1 * 8);
#pragma unroll
            for (int j = 0; j < 4; j++) {
                int c = tid + j * 512, row = c >> 3, q = c & 7;
                cp_async16(Bs + row * 128 + ((q ^ (row & 7)) << 4),
                           Bg + (size_t)row * DIMV + q * 8);
            }
            CP_ASYNC_COMMIT();
        }

        uint32_t Ssm = smem_u32 + cur * STAGE_BYTES;
#pragma unroll
        for (int ks = 0; ks < 4; ks++) {    // k16 per step, chunks {2ks, 2ks+1}
            uint32_t a[4][4];
#pragma unroll
            for (int mt = 0; mt < 4; mt++) {
                uint32_t addr = Ssm + aoff[mt] + ((((ks * 2) | acb) ^ r) << 4);
                ldsm_x4(a[mt][0], a[mt][1], a[mt][2], a[mt][3], addr);
            }
#pragma unroll
            for (int p = 0; p < 2; p++) {
                uint32_t b0, b1, b2, b3;   // {b0,b1} -> nt=2p ; {b2,b3} -> nt=2p+1
                uint32_t addr = Ssm + boff[p] + ((((ks * 2) | bcb) ^ r) << 4);
                ldsm_x4(b0, b1, b2, b3, addr);
#pragma unroll
                for (int mt = 0; mt < 4; mt++) {
                    mma_f16(acc[mt][2 * p],     a[mt][0], a[mt][1], a[mt][2], a[mt][3], b0, b1);
                    mma_f16(acc[mt][2 * p + 1], a[mt][0], a[mt][1], a[mt][2], a[mt][3], b2, b3);
                }
            }
        }
    }

    // ---- fused epilogue: e_partial[row] = sum_n tanh(acc + hb[n]) * w2[n] ----
    int g  = lane >> 2;
    int t4 = lane & 3;
#pragma unroll
    for (int mt = 0; mt < 4; mt++) {
        float e0 = 0.0f, e1 = 0.0f;
#pragma unroll
        for (int nt = 0; nt < 4; nt++) {
            int n = warp_n * 32 + nt * 8 + 2 * t4;
            float h0 = hbs[n], h1 = hbs[n + 1];
            float v0 = w2s[n], v1 = w2s[n + 1];
            e0 += tanh_approx(acc[mt][nt][0] + h0) * v0
                + tanh_approx(acc[mt][nt][1] + h1) * v1;
            e1 += tanh_approx(acc[mt][nt][2] + h0) * v0
                + tanh_approx(acc[mt][nt][3] + h1) * v1;
        }
        e0 += __shfl_xor_sync(0xFFFFFFFF, e0, 1);
        e0 += __shfl_xor_sync(0xFFFFFFFF, e0, 2);
        e1 += __shfl_xor_sync(0xFFFFFFFF, e1, 1);
        e1 += __shfl_xor_sync(0xFFFFFFFF, e1, 2);
        if (t4 == 0) {
            int rl = warp_m * 64 + mt * 16 + g;
            epbuf[warp_n * 128 + rl]     = e0;
            epbuf[warp_n * 128 + rl + 8] = e1;
        }
    }
    __syncthreads();
    if (tid < 128) {
        float s = 0.0f;
#pragma unroll
        for (int w = 0; w < 8; w++) s += epbuf[w * 128 + tid];
        g_ep[(size_t)blockIdx.x * M_TOTAL + m0 + tid] = s;
    }
}

// ============================================================================
// Kernel 3: softmax over S -> alpha. grid 32, 256 threads
// ============================================================================
__global__ void __launch_bounds__(256) softmax_kernel()
{
    __shared__ float se[SEQ];
    __shared__ float red[256];
    int b = blockIdx.x;
    int tid = threadIdx.x;

    float mx = -1e30f;
    for (int s = tid; s < SEQ; s += 256) {
        int row = b * SEQ + s;
        float v = g_ep[row] + g_ep[M_TOTAL + row]
                + g_ep[2 * M_TOTAL + row] + g_ep[3 * M_TOTAL + row];
        se[s] = v;
        mx = fmaxf(mx, v);
    }
    red[tid] = mx;
    __syncthreads();
    for (int s = 128; s > 0; s >>= 1) {
        if (tid < s) red[tid] = fmaxf(red[tid], red[tid + s]);
        __syncthreads();
    }
    mx = red[0];
    __syncthreads();

    float sum = 0.0f;
    for (int s = tid; s < SEQ; s += 256) {
        float ex = __expf(se[s] - mx);
        se[s] = ex;
        sum += ex;
    }
    red[tid] = sum;
    __syncthreads();
    for (int s = 128; s > 0; s >>= 1) {
        if (tid < s) red[tid] += red[tid + s];
        __syncthreads();
    }
    float inv = 1.0f / red[0];
    for (int s = tid; s < SEQ; s += 256)
        g_alpha[b * SEQ + s] = se[s] * inv;
}

// ============================================================================
// Kernel 4: context partials — split S 8 ways (fp32 enc for accuracy)
// grid (8 d-blocks, 32 batch, 8 s-chunks), 128 threads
// ============================================================================
__global__ void __launch_bounds__(128) ctx_partial_kernel(const float* __restrict__ enc)
{
    __shared__ float sa[SEQ / SSPLIT];   // 256
    int b  = blockIdx.y;
    int d  = blockIdx.x * 128 + threadIdx.x;
    int s0 = blockIdx.z * (SEQ / SSPLIT);

    for (int i = threadIdx.x; i < SEQ / SSPLIT; i += 128)
        sa[i] = g_alpha[b * SEQ + s0 + i];
    __syncthreads();

    const float* ep = enc + ((size_t)b * SEQ + s0) * DIMV + d;
    float a0 = 0.f, a1 = 0.f, a2 = 0.f, a3 = 0.f;
#pragma unroll 2
    for (int s = 0; s < SEQ / SSPLIT; s += 8) {
        a0 += sa[s + 0] * ep[(size_t)(s + 0) * DIMV];
        a1 += sa[s + 1] * ep[(size_t)(s + 1) * DIMV];
        a2 += sa[s + 2] * ep[(size_t)(s + 2) * DIMV];
        a3 += sa[s + 3] * ep[(size_t)(s + 3) * DIMV];
        a0 += sa[s + 4] * ep[(size_t)(s + 4) * DIMV];
        a1 += sa[s + 5] * ep[(size_t)(s + 5) * DIMV];
        a2 += sa[s + 6] * ep[(size_t)(s + 6) * DIMV];
        a3 += sa[s + 7] * ep[(size_t)(s + 7) * DIMV];
    }
    g_cpart[((size_t)blockIdx.z * BATCH + b) * DIMV + d] = (a0 + a1) + (a2 + a3);
}

// Kernel 5: combine partials -> out. grid 32 x 1024 threads
__global__ void __launch_bounds__(1024) ctx_combine_kernel(float* __restrict__ out)
{
    int i = blockIdx.x * 1024 + threadIdx.x;   // b*DIMV + d
    float s = 0.0f;
#pragma unroll
    for (int z = 0; z < SSPLIT; z++)
        s += g_cpart[(size_t)z * BATCH * DIMV + i];
    out[i] = s;
}

// ============================================================================
// Launch
// ============================================================================
extern "C" void kernel_launch(void* const* d_in, const int* in_sizes, int n_in,
                              void* d_out, int out_size)
{
    (void)in_sizes; (void)n_in; (void)out_size;
    const float* hidden = (const float*)d_in[0];   // [32, 1024]
    const float* enc    = (const float*)d_in[1];   // [32, 2048, 1024]
    const float* W1     = (const float*)d_in[2];   // [2048, 1024]
    const float* b1     = (const float*)d_in[3];   // [1024]
    const float* w2     = (const float*)d_in[4];   // [1024]
    float* out          = (float*)d_out;           // [32, 1024]

    cudaFuncSetAttribute(gemm_tanh_kernel,
                         cudaFuncAttributeMaxDynamicSharedMemorySize, SMEM_GEMM);

    enc16_kernel<<<8192, 1024>>>(enc);
    transpose_kernel<<<dim3(32, 32), dim3(32, 8)>>>(W1);
    hidproj_kernel<<<dim3(32, 8), 128>>>(hidden, W1, b1);
    gemm_tanh_kernel<<<dim3(N_TILES, M_TILES), 512, SMEM_GEMM>>>(w2);
    softmax_kernel<<<32, 256>>>();
    ctx_partial_kernel<<<dim3(8, 32, 8), 128>>>(enc);
    ctx_combine_kernel<<<32, 1024>>>(out);
}